// round 10
// baseline (speedup 1.0000x reference)
#include <cuda_runtime.h>
#include <cuda_bf16.h>
#include <math.h>
#include <stdint.h>

#define N_NODES 100000
#define N_EDGES 640000

// ---------------- scratch (device globals) ----------------------------------
__device__ __nv_bfloat16 g_A1hi[(size_t)N_NODES * 256];
__device__ __nv_bfloat16 g_A1lo[(size_t)N_NODES * 256];
__device__ __nv_bfloat16 g_uhhi[(size_t)N_NODES * 256];  // bsplit(relu(c1+b1)), unnormalized
__device__ __nv_bfloat16 g_uhlo[(size_t)N_NODES * 256];
__device__ float g_ssq[(size_t)(N_NODES + 128) * 2];      // per-row, per-half sum of squares
__device__ float g_p2 [(size_t)N_NODES * 128];
__device__ float g_r2b[(size_t)N_NODES * 128];
__device__ float g_p3 [(size_t)N_NODES * 2];
__device__ float g_r3 [(size_t)N_NODES * 2];
__device__ int   g_deg[N_NODES];          // zero-init at load; scan re-zeroes each run
__device__ int   g_rowptr[N_NODES + 1];
__device__ int   g_cursor[N_NODES];       // absolute cursors (scan sets = rowptr)
__device__ int   g_csr[N_EDGES];
__device__ __nv_bfloat16 g_W1p[256 * 768];   // [Whi|Wlo|Whi] K-concat, K-major
__device__ __nv_bfloat16 g_W2p[256 * 768];
__device__ float g_bp2[256];

__device__ __forceinline__ uint32_t smem_u32(const void* p) {
    uint32_t a;
    asm("{ .reg .u64 t; cvta.to.shared.u64 t, %1; cvt.u32.u64 %0, t; }"
        : "=r"(a) : "l"(p));
    return a;
}

__device__ __forceinline__ void bsplit(float v, __nv_bfloat16& hi, __nv_bfloat16& lo) {
    hi = __float2bfloat16(v);
    lo = __float2bfloat16(v - __bfloat162float(hi));
}

// ---------------- edge dtype: per-block detection ---------------------------
__device__ __forceinline__ int detect_is64_block(const void* edges) {
    const int* p = (const int*)edges;
    int nz = __syncthreads_or(p[2 * (threadIdx.x & 255) + 1] != 0);
    return nz == 0;
}
__device__ __forceinline__ int edge_at(const void* p, long long i, int is64) {
    if (is64) return (int)((const long long*)p)[i];
    return ((const int*)p)[i];
}

// ---------------- pack weights (no zeroing needed anymore) ------------------
__global__ void pack_kernel(const float* __restrict__ W1l, const float* __restrict__ W1r,
                            const float* __restrict__ W2l, const float* __restrict__ W2r,
                            const float* __restrict__ b2) {
    int idx = blockIdx.x * blockDim.x + threadIdx.x;
    if (idx >= 256 * 768) return;
    int n = idx / 768, k7 = idx % 768;
    int seg = k7 >> 8, k = k7 & 255;
    float v1 = (k < 128) ? W1l[n * 128 + k] : W1r[n * 128 + (k - 128)];
    float v2 = (n < 128) ? W2l[n * 256 + k] : W2r[(n - 128) * 256 + k];
    __nv_bfloat16 h1, l1, h2, l2;
    bsplit(v1, h1, l1);
    bsplit(v2, h2, l2);
    g_W1p[idx] = (seg == 1) ? l1 : h1;
    g_W2p[idx] = (seg == 1) ? l2 : h2;
    if (idx < 256) g_bp2[idx] = (idx < 128) ? 0.0f : b2[idx - 128];
}

__global__ void count_kernel(const void* edges) {
    int is64 = detect_is64_block(edges);
    int e = blockIdx.x * blockDim.x + threadIdx.x;
    if (e < N_EDGES) atomicAdd(&g_deg[edge_at(edges, (long long)N_EDGES + e, is64)], 1);
}

// scan: rowptr = exclusive prefix of deg; cursor = rowptr (absolute);
// deg re-zeroed for the next graph replay (zero-init .bss covers the first).
__global__ void scan_kernel() {
    const int T = 1024;
    int t = threadIdx.x;
    const int per = (N_NODES + T - 1) / T;
    int s = t * per;
    int e = min(s + per, N_NODES);
    if (s > e) s = e;
    int sum = 0;
    for (int i = s; i < e; i++) sum += g_deg[i];
    __shared__ int sh[T];
    sh[t] = sum;
    __syncthreads();
    for (int off = 1; off < T; off <<= 1) {
        int v = (t >= off) ? sh[t - off] : 0;
        __syncthreads();
        sh[t] += v;
        __syncthreads();
    }
    int run = sh[t] - sum;
    for (int i = s; i < e; i++) {
        int d = g_deg[i];
        g_rowptr[i] = run;
        g_cursor[i] = run;
        g_deg[i] = 0;
        run += d;
    }
    if (e == N_NODES) g_rowptr[N_NODES] = run;
}

__global__ void fill_kernel(const void* edges) {
    int is64 = detect_is64_block(edges);
    int e = blockIdx.x * blockDim.x + threadIdx.x;
    if (e >= N_EDGES) return;
    int s = edge_at(edges, e, is64);
    int d = edge_at(edges, (long long)N_EDGES + e, is64);
    int pos = atomicAdd(&g_cursor[d], 1);
    g_csr[pos] = s;
}

// ---------------- prep1: own-x split (cols 128-255) + neighbor mean (0-127) -
__global__ void prep1_kernel(const float* __restrict__ x) {
    int gw = (blockIdx.x * blockDim.x + threadIdx.x) >> 5;
    int lane = threadIdx.x & 31;
    if (gw >= N_NODES) return;

    {
        float4 xv = __ldg((const float4*)(x + (size_t)gw * 128 + lane * 4));
        __nv_bfloat16 hx, lx, hy, ly, hz, lz, hw, lw;
        bsplit(xv.x, hx, lx); bsplit(xv.y, hy, ly);
        bsplit(xv.z, hz, lz); bsplit(xv.w, hw, lw);
        size_t o = (size_t)gw * 256 + 128 + lane * 4;
        __nv_bfloat162 t;
        t.x = hx; t.y = hy; *(__nv_bfloat162*)(g_A1hi + o) = t;
        t.x = hz; t.y = hw; *(__nv_bfloat162*)(g_A1hi + o + 2) = t;
        t.x = lx; t.y = ly; *(__nv_bfloat162*)(g_A1lo + o) = t;
        t.x = lz; t.y = lw; *(__nv_bfloat162*)(g_A1lo + o + 2) = t;
    }

    int beg = g_rowptr[gw], end = g_rowptr[gw + 1];
    float4 acc = make_float4(0.f, 0.f, 0.f, 0.f);
    int j = beg;
    for (; j + 3 < end; j += 4) {            // MLP=4
        int s0 = g_csr[j],     s1 = g_csr[j + 1];
        int s2 = g_csr[j + 2], s3 = g_csr[j + 3];
        float4 v0 = __ldg((const float4*)(x + (size_t)s0 * 128 + lane * 4));
        float4 v1 = __ldg((const float4*)(x + (size_t)s1 * 128 + lane * 4));
        float4 v2 = __ldg((const float4*)(x + (size_t)s2 * 128 + lane * 4));
        float4 v3 = __ldg((const float4*)(x + (size_t)s3 * 128 + lane * 4));
        acc.x += (v0.x + v1.x) + (v2.x + v3.x);
        acc.y += (v0.y + v1.y) + (v2.y + v3.y);
        acc.z += (v0.z + v1.z) + (v2.z + v3.z);
        acc.w += (v0.w + v1.w) + (v2.w + v3.w);
    }
    for (; j < end; j++) {
        int s0 = g_csr[j];
        float4 v0 = __ldg((const float4*)(x + (size_t)s0 * 128 + lane * 4));
        acc.x += v0.x; acc.y += v0.y; acc.z += v0.z; acc.w += v0.w;
    }
    float inv = 1.0f / (float)max(end - beg, 1);
    acc.x *= inv; acc.y *= inv; acc.z *= inv; acc.w *= inv;
    __nv_bfloat16 hx, lx, hy, ly, hz, lz, hw, lw;
    bsplit(acc.x, hx, lx); bsplit(acc.y, hy, ly);
    bsplit(acc.z, hz, lz); bsplit(acc.w, hw, lw);
    size_t o = (size_t)gw * 256 + lane * 4;
    __nv_bfloat162 t;
    t.x = hx; t.y = hy; *(__nv_bfloat162*)(g_A1hi + o) = t;
    t.x = hz; t.y = hw; *(__nv_bfloat162*)(g_A1hi + o + 2) = t;
    t.x = lx; t.y = ly; *(__nv_bfloat162*)(g_A1lo + o) = t;
    t.x = lz; t.y = lw; *(__nv_bfloat162*)(g_A1lo + o + 2) = t;
}

// ---------------- bf16 mma.sync GEMM (round-6 proven shape) -----------------
// CTA tile 128x128, 8 warps (4x2), warp tile 32x64, BK=32, cp.async dbl-buf.
// grid dim3(MB, 2): blockIdx.y = N-half.
// EPI=1: v = acc + bias; per-row ssq -> g_ssq[row*2+y]; write bsplit(relu(v)).
// EPI=2: out = s_row * acc + bias (deferred layer-1 normalization).
#define SMEM_STRIDE 40
template <int EPI>
__global__ void __launch_bounds__(256)
gemm_mma(const __nv_bfloat16* __restrict__ Ahi, const __nv_bfloat16* __restrict__ Alo,
         const __nv_bfloat16* __restrict__ Wp, const float* __restrict__ bias,
         void* __restrict__ o0, void* __restrict__ o1)
{
    __shared__ __align__(16) __nv_bfloat16 Asb[2][128 * SMEM_STRIDE];
    __shared__ __align__(16) __nv_bfloat16 Bsb[2][128 * SMEM_STRIDE];
    __shared__ float sbias[128];
    __shared__ float ssqs[128];

    const int tid = threadIdx.x;
    const int wid = tid >> 5, lane = tid & 31;
    const int m0 = blockIdx.x * 128;
    const int n0g = blockIdx.y * 128;
    const int mw = wid >> 1;
    const int nw = wid & 1;

    if (tid < 128) { sbias[tid] = __ldg(&bias[n0g + tid]); ssqs[tid] = 0.f; }

    const uint32_t As_base = smem_u32(Asb);
    const uint32_t Bs_base = smem_u32(Bsb);
    const uint32_t BUFB = 128 * SMEM_STRIDE * 2;

    const int r0c = tid >> 2, sub0 = tid & 3;
    const int r1c = (tid + 256) >> 2, sub1 = (tid + 256) & 3;

#define LOAD_TILE(b, kt) do {                                                   \
    int k0 = (kt) * 32;                                                         \
    const __nv_bfloat16* Asrc = ((k0 >> 8) < 2) ? Ahi : Alo;                    \
    int kc = k0 & 255;                                                          \
    uint32_t Ad = As_base + (b) * BUFB;                                         \
    uint32_t Bd = Bs_base + (b) * BUFB;                                         \
    {                                                                           \
        int grow = m0 + r0c;                                                    \
        const void* src = Asrc + (size_t)grow * 256 + kc + sub0 * 8;            \
        int pb = (grow < N_NODES) ? 16 : 0;                                     \
        asm volatile("cp.async.cg.shared.global [%0], [%1], 16, %2;"            \
            :: "r"(Ad + r0c * 80 + sub0 * 16), "l"(src), "r"(pb));              \
        grow = m0 + r1c;                                                        \
        src = Asrc + (size_t)grow * 256 + kc + sub1 * 8;                        \
        pb = (grow < N_NODES) ? 16 : 0;                                         \
        asm volatile("cp.async.cg.shared.global [%0], [%1], 16, %2;"            \
            :: "r"(Ad + r1c * 80 + sub1 * 16), "l"(src), "r"(pb));              \
    }                                                                           \
    {                                                                           \
        const void* src = Wp + (size_t)(n0g + r0c) * 768 + k0 + sub0 * 8;       \
        asm volatile("cp.async.cg.shared.global [%0], [%1], 16;"                \
            :: "r"(Bd + r0c * 80 + sub0 * 16), "l"(src));                       \
        src = Wp + (size_t)(n0g + r1c) * 768 + k0 + sub1 * 8;                   \
        asm volatile("cp.async.cg.shared.global [%0], [%1], 16;"                \
            :: "r"(Bd + r1c * 80 + sub1 * 16), "l"(src));                       \
    }                                                                           \
    asm volatile("cp.async.commit_group;" ::: "memory");                        \
} while (0)

    float acc[2][8][4];
#pragma unroll
    for (int mt = 0; mt < 2; mt++)
#pragma unroll
        for (int nt = 0; nt < 8; nt++)
#pragma unroll
            for (int v = 0; v < 4; v++) acc[mt][nt][v] = 0.f;

    LOAD_TILE(0, 0);

    const int NK = 24;
    for (int kt = 0; kt < NK; kt++) {
        int b = kt & 1;
        if (kt + 1 < NK) {
            LOAD_TILE(b ^ 1, kt + 1);
            asm volatile("cp.async.wait_group 1;" ::: "memory");
        } else {
            asm volatile("cp.async.wait_group 0;" ::: "memory");
        }
        __syncthreads();

        uint32_t Au = As_base + b * BUFB;
        uint32_t Bu = Bs_base + b * BUFB;
#pragma unroll
        for (int kk = 0; kk < 32; kk += 16) {
            uint32_t a[2][4];
#pragma unroll
            for (int mt = 0; mt < 2; mt++) {
                uint32_t addr = Au + (mw * 32 + mt * 16 + (lane & 15)) * 80
                              + (kk + ((lane >> 4) << 3)) * 2;
                asm volatile("ldmatrix.sync.aligned.m8n8.x4.shared.b16 {%0,%1,%2,%3}, [%4];"
                    : "=r"(a[mt][0]), "=r"(a[mt][1]), "=r"(a[mt][2]), "=r"(a[mt][3])
                    : "r"(addr));
            }
            uint32_t bf[4][4];
#pragma unroll
            for (int nq = 0; nq < 4; nq++) {
                uint32_t addr = Bu + (nw * 64 + nq * 16 + (lane & 7) + ((lane >> 4) << 3)) * 80
                              + (kk + (((lane >> 3) & 1) << 3)) * 2;
                asm volatile("ldmatrix.sync.aligned.m8n8.x4.shared.b16 {%0,%1,%2,%3}, [%4];"
                    : "=r"(bf[nq][0]), "=r"(bf[nq][1]), "=r"(bf[nq][2]), "=r"(bf[nq][3])
                    : "r"(addr));
            }
#pragma unroll
            for (int mt = 0; mt < 2; mt++)
#pragma unroll
                for (int nt = 0; nt < 8; nt++) {
                    int nq = nt >> 1, hv = (nt & 1) << 1;
                    asm volatile(
                        "mma.sync.aligned.m16n8k16.row.col.f32.bf16.bf16.f32 "
                        "{%0,%1,%2,%3}, {%4,%5,%6,%7}, {%8,%9}, {%0,%1,%2,%3};"
                        : "+f"(acc[mt][nt][0]), "+f"(acc[mt][nt][1]),
                          "+f"(acc[mt][nt][2]), "+f"(acc[mt][nt][3])
                        : "r"(a[mt][0]), "r"(a[mt][1]), "r"(a[mt][2]), "r"(a[mt][3]),
                          "r"(bf[nq][hv]), "r"(bf[nq][hv + 1]));
                }
        }
        __syncthreads();
    }
#undef LOAD_TILE

    const int lr = lane >> 2, lc = (lane & 3) * 2;

    if (EPI == 1) {
#pragma unroll
        for (int mt = 0; mt < 2; mt++) {
            float sa = 0.f, sb = 0.f;
#pragma unroll
            for (int nt = 0; nt < 8; nt++) {
                int col = nw * 64 + nt * 8 + lc;
                float v0 = acc[mt][nt][0] + sbias[col];
                float v1 = acc[mt][nt][1] + sbias[col + 1];
                float v2 = acc[mt][nt][2] + sbias[col];
                float v3 = acc[mt][nt][3] + sbias[col + 1];
                acc[mt][nt][0] = v0; acc[mt][nt][1] = v1;
                acc[mt][nt][2] = v2; acc[mt][nt][3] = v3;
                sa += v0 * v0 + v1 * v1;
                sb += v2 * v2 + v3 * v3;
            }
            int rla = mw * 32 + mt * 16 + lr;
            atomicAdd(&ssqs[rla], sa);
            atomicAdd(&ssqs[rla + 8], sb);
        }
        __syncthreads();
        if (tid < 128) {
            int gr = m0 + tid;
            if (gr < N_NODES) g_ssq[(size_t)gr * 2 + blockIdx.y] = ssqs[tid];
        }
        __nv_bfloat16* H = g_uhhi;
        __nv_bfloat16* L = g_uhlo;
#pragma unroll
        for (int mt = 0; mt < 2; mt++) {
            int ra = m0 + mw * 32 + mt * 16 + lr;
            int rb = ra + 8;
#pragma unroll
            for (int nt = 0; nt < 8; nt++) {
                int gcol = n0g + nw * 64 + nt * 8 + lc;
                if (ra < N_NODES) {
                    float v0 = fmaxf(acc[mt][nt][0], 0.f);
                    float v1 = fmaxf(acc[mt][nt][1], 0.f);
                    __nv_bfloat16 h0, l0, h1, l1;
                    bsplit(v0, h0, l0); bsplit(v1, h1, l1);
                    __nv_bfloat162 hh; hh.x = h0; hh.y = h1;
                    __nv_bfloat162 ll; ll.x = l0; ll.y = l1;
                    *(__nv_bfloat162*)(H + (size_t)ra * 256 + gcol) = hh;
                    *(__nv_bfloat162*)(L + (size_t)ra * 256 + gcol) = ll;
                }
                if (rb < N_NODES) {
                    float v0 = fmaxf(acc[mt][nt][2], 0.f);
                    float v1 = fmaxf(acc[mt][nt][3], 0.f);
                    __nv_bfloat16 h0, l0, h1, l1;
                    bsplit(v0, h0, l0); bsplit(v1, h1, l1);
                    __nv_bfloat162 hh; hh.x = h0; hh.y = h1;
                    __nv_bfloat162 ll; ll.x = l0; ll.y = l1;
                    *(__nv_bfloat162*)(H + (size_t)rb * 256 + gcol) = hh;
                    *(__nv_bfloat162*)(L + (size_t)rb * 256 + gcol) = ll;
                }
            }
        }
    } else {
        float* o = (blockIdx.y == 0) ? (float*)o0 : (float*)o1;
#pragma unroll
        for (int mt = 0; mt < 2; mt++) {
            int ra = m0 + mw * 32 + mt * 16 + lr;
            int rb = ra + 8;
            float sA = 0.f, sB = 0.f;
            if (ra < N_NODES) {
                float t = g_ssq[(size_t)ra * 2] + g_ssq[(size_t)ra * 2 + 1];
                sA = 1.0f / fmaxf(sqrtf(t), 1e-12f);
            }
            if (rb < N_NODES) {
                float t = g_ssq[(size_t)rb * 2] + g_ssq[(size_t)rb * 2 + 1];
                sB = 1.0f / fmaxf(sqrtf(t), 1e-12f);
            }
#pragma unroll
            for (int nt = 0; nt < 8; nt++) {
                int col = nw * 64 + nt * 8 + lc;
                float b0v = sbias[col], b1v = sbias[col + 1];
                if (ra < N_NODES) {
                    float2 v;
                    v.x = acc[mt][nt][0] * sA + b0v;
                    v.y = acc[mt][nt][1] * sA + b1v;
                    *(float2*)(o + (size_t)ra * 128 + col) = v;
                }
                if (rb < N_NODES) {
                    float2 v;
                    v.x = acc[mt][nt][2] * sB + b0v;
                    v.y = acc[mt][nt][3] * sB + b1v;
                    *(float2*)(o + (size_t)rb * 128 + col) = v;
                }
            }
        }
    }
}

// ------- gather2 + norm2 + layer3 projection fused (h2 never hits gmem) ----
__global__ void gather_l3_kernel(const float* __restrict__ W3l,
                                 const float* __restrict__ W3r) {
    int gw = (blockIdx.x * blockDim.x + threadIdx.x) >> 5;
    int lane = threadIdx.x & 31;
    if (gw >= N_NODES) return;
    int beg = g_rowptr[gw], end = g_rowptr[gw + 1];
    float4 acc = make_float4(0.f, 0.f, 0.f, 0.f);
    int j = beg;
    for (; j + 3 < end; j += 4) {            // MLP=4
        int s0 = g_csr[j],     s1 = g_csr[j + 1];
        int s2 = g_csr[j + 2], s3 = g_csr[j + 3];
        float4 v0 = __ldg((const float4*)(g_p2 + (size_t)s0 * 128 + lane * 4));
        float4 v1 = __ldg((const float4*)(g_p2 + (size_t)s1 * 128 + lane * 4));
        float4 v2 = __ldg((const float4*)(g_p2 + (size_t)s2 * 128 + lane * 4));
        float4 v3 = __ldg((const float4*)(g_p2 + (size_t)s3 * 128 + lane * 4));
        acc.x += (v0.x + v1.x) + (v2.x + v3.x);
        acc.y += (v0.y + v1.y) + (v2.y + v3.y);
        acc.z += (v0.z + v1.z) + (v2.z + v3.z);
        acc.w += (v0.w + v1.w) + (v2.w + v3.w);
    }
    for (; j < end; j++) {
        int s0 = g_csr[j];
        float4 v0 = __ldg((const float4*)(g_p2 + (size_t)s0 * 128 + lane * 4));
        acc.x += v0.x; acc.y += v0.y; acc.z += v0.z; acc.w += v0.w;
    }
    float inv = 1.0f / (float)max(end - beg, 1);
    float4 rb = *(const float4*)(g_r2b + (size_t)gw * 128 + lane * 4);
    float4 u;
    u.x = acc.x * inv + rb.x; u.y = acc.y * inv + rb.y;
    u.z = acc.z * inv + rb.z; u.w = acc.w * inv + rb.w;
    float ss = u.x * u.x + u.y * u.y + u.z * u.z + u.w * u.w;
#pragma unroll
    for (int o = 16; o; o >>= 1) ss += __shfl_xor_sync(0xFFFFFFFFu, ss, o);
    float s = 1.0f / fmaxf(sqrtf(ss), 1e-12f);
    u.x = fmaxf(u.x * s, 0.f); u.y = fmaxf(u.y * s, 0.f);
    u.z = fmaxf(u.z * s, 0.f); u.w = fmaxf(u.w * s, 0.f);

    int k = lane * 4;
    float4 wl0 = __ldg((const float4*)(W3l + k));
    float4 wl1 = __ldg((const float4*)(W3l + 128 + k));
    float4 wr0 = __ldg((const float4*)(W3r + k));
    float4 wr1 = __ldg((const float4*)(W3r + 128 + k));
    float a0 = u.x * wl0.x + u.y * wl0.y + u.z * wl0.z + u.w * wl0.w;
    float a1 = u.x * wl1.x + u.y * wl1.y + u.z * wl1.z + u.w * wl1.w;
    float b0 = u.x * wr0.x + u.y * wr0.y + u.z * wr0.z + u.w * wr0.w;
    float b1 = u.x * wr1.x + u.y * wr1.y + u.z * wr1.z + u.w * wr1.w;
#pragma unroll
    for (int o = 16; o; o >>= 1) {
        a0 += __shfl_xor_sync(0xFFFFFFFFu, a0, o);
        a1 += __shfl_xor_sync(0xFFFFFFFFu, a1, o);
        b0 += __shfl_xor_sync(0xFFFFFFFFu, b0, o);
        b1 += __shfl_xor_sync(0xFFFFFFFFu, b1, o);
    }
    if (lane == 0) {
        g_p3[2 * gw + 0] = a0; g_p3[2 * gw + 1] = a1;
        g_r3[2 * gw + 0] = b0; g_r3[2 * gw + 1] = b1;
    }
}

__global__ void l3final_kernel(const float* __restrict__ b3,
                               float* __restrict__ out) {
    int n = blockIdx.x * blockDim.x + threadIdx.x;
    if (n >= N_NODES) return;
    int beg = g_rowptr[n], end = g_rowptr[n + 1];
    float s0 = 0.f, s1 = 0.f;
    int j = beg;
    for (; j + 1 < end; j += 2) {
        int sa = g_csr[j], sb = g_csr[j + 1];
        float2 va = __ldg((const float2*)(g_p3 + 2 * (size_t)sa));
        float2 vb = __ldg((const float2*)(g_p3 + 2 * (size_t)sb));
        s0 += va.x + vb.x; s1 += va.y + vb.y;
    }
    if (j < end) {
        float2 v = __ldg((const float2*)(g_p3 + 2 * (size_t)g_csr[j]));
        s0 += v.x; s1 += v.y;
    }
    float inv = 1.0f / (float)max(end - beg, 1);
    float v0 = s0 * inv + g_r3[2 * n + 0] + __ldg(&b3[0]);
    float v1 = s1 * inv + g_r3[2 * n + 1] + __ldg(&b3[1]);
    float nrm = sqrtf(v0 * v0 + v1 * v1);
    float sc = 1.0f / fmaxf(nrm, 1e-12f);
    v0 *= sc; v1 *= sc;
    float mx = fmaxf(v0, v1);
    float lse = mx + logf(expf(v0 - mx) + expf(v1 - mx));
    out[2 * n + 0] = v0 - lse;
    out[2 * n + 1] = v1 - lse;
}

// ---------------- launch ----------------------------------------------------
extern "C" void kernel_launch(void* const* d_in, const int* in_sizes, int n_in,
                              void* d_out, int out_size) {
    const float* x   = (const float*)d_in[0];
    const void*  edg = d_in[1];
    const float* W1l = (const float*)d_in[2];
    const float* W1r = (const float*)d_in[3];
    const float* b1  = (const float*)d_in[4];
    const float* W2l = (const float*)d_in[5];
    const float* W2r = (const float*)d_in[6];
    const float* b2  = (const float*)d_in[7];
    const float* W3l = (const float*)d_in[8];
    const float* W3r = (const float*)d_in[9];
    const float* b3  = (const float*)d_in[10];
    float* out = (float*)d_out;

    void *a1h, *a1l, *uhh, *uhl, *p2p, *r2p, *w1p, *w2p, *bp2;
    cudaGetSymbolAddress(&a1h, g_A1hi);
    cudaGetSymbolAddress(&a1l, g_A1lo);
    cudaGetSymbolAddress(&uhh, g_uhhi);
    cudaGetSymbolAddress(&uhl, g_uhlo);
    cudaGetSymbolAddress(&p2p, g_p2);
    cudaGetSymbolAddress(&r2p, g_r2b);
    cudaGetSymbolAddress(&w1p, g_W1p);
    cudaGetSymbolAddress(&w2p, g_W2p);
    cudaGetSymbolAddress(&bp2, g_bp2);

    const int EB = (N_EDGES + 255) / 256;
    const int WARP_BLKS = (N_NODES * 32 + 255) / 256;
    const int MB = (N_NODES + 127) / 128;   // 782

    // prologue: pack, CSR build (self-cleaning: scan re-zeroes deg, sets cursor)
    pack_kernel<<<768, 256>>>(W1l, W1r, W2l, W2r, b2);
    count_kernel<<<EB, 256>>>(edg);
    scan_kernel<<<1, 1024>>>();
    fill_kernel<<<EB, 256>>>(edg);

    // Layer 1: prep + GEMM with fused relu/bsplit epilogue (+ssq partials)
    prep1_kernel<<<WARP_BLKS, 256>>>(x);
    gemm_mma<1><<<dim3(MB, 2), 256>>>((const __nv_bfloat16*)a1h, (const __nv_bfloat16*)a1l,
                                      (const __nv_bfloat16*)w1p, b1,
                                      (void*)0, (void*)0);

    // Layer 2: GEMM with deferred layer-1 normalization in epilogue
    gemm_mma<2><<<dim3(MB, 2), 256>>>((const __nv_bfloat16*)uhh, (const __nv_bfloat16*)uhl,
                                      (const __nv_bfloat16*)w2p, (const float*)bp2,
                                      p2p, r2p);
    gather_l3_kernel<<<WARP_BLKS, 256>>>(W3l, W3r);

    // Layer 3 finalize
    l3final_kernel<<<(N_NODES + 255) / 256, 256>>>(b3, out);
}

// round 11
// speedup vs baseline: 1.1848x; 1.1848x over previous
#include <cuda_runtime.h>
#include <cuda_bf16.h>
#include <math.h>
#include <stdint.h>

#define N_NODES 100000
#define N_EDGES 640000

// ---------------- scratch (device globals) ----------------------------------
__device__ __nv_bfloat16 g_A1hi[(size_t)N_NODES * 256];
__device__ __nv_bfloat16 g_A1lo[(size_t)N_NODES * 256];
__device__ __nv_bfloat16 g_uhhi[(size_t)N_NODES * 256];  // bsplit(relu(c1+b1)), unnormalized
__device__ __nv_bfloat16 g_uhlo[(size_t)N_NODES * 256];
__device__ float g_ssq[(size_t)(N_NODES + 128) * 2];      // per-row, per-half sum of squares
__device__ float g_p2 [(size_t)N_NODES * 128];
__device__ float g_r2b[(size_t)N_NODES * 128];
__device__ float g_p3 [(size_t)N_NODES * 2];
__device__ float g_r3 [(size_t)N_NODES * 2];
__device__ int   g_deg[N_NODES];
__device__ int   g_rowptr[N_NODES + 1];
__device__ int   g_cursor[N_NODES];
__device__ int   g_csr[N_EDGES];
__device__ __nv_bfloat16 g_W1p[256 * 768];   // [Whi|Wlo|Whi] K-concat, K-major
__device__ __nv_bfloat16 g_W2p[256 * 768];
__device__ float g_bp2[256];

__device__ __forceinline__ uint32_t smem_u32(const void* p) {
    uint32_t a;
    asm("{ .reg .u64 t; cvta.to.shared.u64 t, %1; cvt.u32.u64 %0, t; }"
        : "=r"(a) : "l"(p));
    return a;
}

__device__ __forceinline__ void bsplit(float v, __nv_bfloat16& hi, __nv_bfloat16& lo) {
    hi = __float2bfloat16(v);
    lo = __float2bfloat16(v - __bfloat162float(hi));
}

// ---------------- edge dtype: per-block detection ---------------------------
__device__ __forceinline__ int detect_is64_block(const void* edges) {
    const int* p = (const int*)edges;
    int nz = __syncthreads_or(p[2 * (threadIdx.x & 255) + 1] != 0);
    return nz == 0;
}
__device__ __forceinline__ int edge_at(const void* p, long long i, int is64) {
    if (is64) return (int)((const long long*)p)[i];
    return ((const int*)p)[i];
}

// ---------------- pack weights + zero deg/cursor -----------------------------
__global__ void pack_kernel(const float* __restrict__ W1l, const float* __restrict__ W1r,
                            const float* __restrict__ W2l, const float* __restrict__ W2r,
                            const float* __restrict__ b2) {
    int idx = blockIdx.x * blockDim.x + threadIdx.x;
    if (idx < N_NODES) { g_deg[idx] = 0; g_cursor[idx] = 0; }
    if (idx >= 256 * 768) return;
    int n = idx / 768, k7 = idx % 768;
    int seg = k7 >> 8, k = k7 & 255;
    float v1 = (k < 128) ? W1l[n * 128 + k] : W1r[n * 128 + (k - 128)];
    float v2 = (n < 128) ? W2l[n * 256 + k] : W2r[(n - 128) * 256 + k];
    __nv_bfloat16 h1, l1, h2, l2;
    bsplit(v1, h1, l1);
    bsplit(v2, h2, l2);
    g_W1p[idx] = (seg == 1) ? l1 : h1;
    g_W2p[idx] = (seg == 1) ? l2 : h2;
    if (idx < 256) g_bp2[idx] = (idx < 128) ? 0.0f : b2[idx - 128];
}

__global__ void count_kernel(const void* edges) {
    int is64 = detect_is64_block(edges);
    int e = blockIdx.x * blockDim.x + threadIdx.x;
    if (e < N_EDGES) atomicAdd(&g_deg[edge_at(edges, (long long)N_EDGES + e, is64)], 1);
}

__global__ void scan_kernel() {
    const int T = 1024;
    int t = threadIdx.x;
    const int per = (N_NODES + T - 1) / T;
    int s = t * per;
    int e = min(s + per, N_NODES);
    if (s > e) s = e;
    int sum = 0;
    for (int i = s; i < e; i++) sum += g_deg[i];
    __shared__ int sh[T];
    sh[t] = sum;
    __syncthreads();
    for (int off = 1; off < T; off <<= 1) {
        int v = (t >= off) ? sh[t - off] : 0;
        __syncthreads();
        sh[t] += v;
        __syncthreads();
    }
    int run = sh[t] - sum;
    for (int i = s; i < e; i++) { g_rowptr[i] = run; run += g_deg[i]; }
    if (e == N_NODES) g_rowptr[N_NODES] = run;
}

__global__ void fill_kernel(const void* edges) {
    int is64 = detect_is64_block(edges);
    int e = blockIdx.x * blockDim.x + threadIdx.x;
    if (e >= N_EDGES) return;
    int s = edge_at(edges, e, is64);
    int d = edge_at(edges, (long long)N_EDGES + e, is64);
    int pos = g_rowptr[d] + atomicAdd(&g_cursor[d], 1);
    g_csr[pos] = s;
}

// ---------------- prep1: own-x split (cols 128-255) + neighbor mean (0-127) -
__global__ void prep1_kernel(const float* __restrict__ x) {
    int gw = (blockIdx.x * blockDim.x + threadIdx.x) >> 5;
    int lane = threadIdx.x & 31;
    if (gw >= N_NODES) return;

    {
        float4 xv = __ldg((const float4*)(x + (size_t)gw * 128 + lane * 4));
        __nv_bfloat16 hx, lx, hy, ly, hz, lz, hw, lw;
        bsplit(xv.x, hx, lx); bsplit(xv.y, hy, ly);
        bsplit(xv.z, hz, lz); bsplit(xv.w, hw, lw);
        size_t o = (size_t)gw * 256 + 128 + lane * 4;
        __nv_bfloat162 t;
        t.x = hx; t.y = hy; *(__nv_bfloat162*)(g_A1hi + o) = t;
        t.x = hz; t.y = hw; *(__nv_bfloat162*)(g_A1hi + o + 2) = t;
        t.x = lx; t.y = ly; *(__nv_bfloat162*)(g_A1lo + o) = t;
        t.x = lz; t.y = lw; *(__nv_bfloat162*)(g_A1lo + o + 2) = t;
    }

    int beg = g_rowptr[gw], end = g_rowptr[gw + 1];
    float4 acc = make_float4(0.f, 0.f, 0.f, 0.f);
    int j = beg;
    for (; j + 1 < end; j += 2) {
        int s0 = g_csr[j], s1 = g_csr[j + 1];
        float4 v0 = __ldg((const float4*)(x + (size_t)s0 * 128 + lane * 4));
        float4 v1 = __ldg((const float4*)(x + (size_t)s1 * 128 + lane * 4));
        acc.x += v0.x + v1.x; acc.y += v0.y + v1.y;
        acc.z += v0.z + v1.z; acc.w += v0.w + v1.w;
    }
    if (j < end) {
        int s0 = g_csr[j];
        float4 v0 = __ldg((const float4*)(x + (size_t)s0 * 128 + lane * 4));
        acc.x += v0.x; acc.y += v0.y; acc.z += v0.z; acc.w += v0.w;
    }
    float inv = 1.0f / (float)max(end - beg, 1);
    acc.x *= inv; acc.y *= inv; acc.z *= inv; acc.w *= inv;
    __nv_bfloat16 hx, lx, hy, ly, hz, lz, hw, lw;
    bsplit(acc.x, hx, lx); bsplit(acc.y, hy, ly);
    bsplit(acc.z, hz, lz); bsplit(acc.w, hw, lw);
    size_t o = (size_t)gw * 256 + lane * 4;
    __nv_bfloat162 t;
    t.x = hx; t.y = hy; *(__nv_bfloat162*)(g_A1hi + o) = t;
    t.x = hz; t.y = hw; *(__nv_bfloat162*)(g_A1hi + o + 2) = t;
    t.x = lx; t.y = ly; *(__nv_bfloat162*)(g_A1lo + o) = t;
    t.x = lz; t.y = lw; *(__nv_bfloat162*)(g_A1lo + o + 2) = t;
}

// ---------------- bf16 mma.sync GEMM (round-6 proven shape) -----------------
// CTA tile 128x128, 8 warps (4x2), warp tile 32x64, BK=32, cp.async dbl-buf.
// grid dim3(MB, 2): blockIdx.y = N-half.
// EPI=1: v = acc + bias; per-row ssq -> g_ssq[row*2+y]; write bsplit(relu(v)).
// EPI=2: out = s_row * acc + bias (deferred layer-1 normalization).
#define SMEM_STRIDE 40
template <int EPI>
__global__ void __launch_bounds__(256)
gemm_mma(const __nv_bfloat16* __restrict__ Ahi, const __nv_bfloat16* __restrict__ Alo,
         const __nv_bfloat16* __restrict__ Wp, const float* __restrict__ bias,
         void* __restrict__ o0, void* __restrict__ o1)
{
    __shared__ __align__(16) __nv_bfloat16 Asb[2][128 * SMEM_STRIDE];
    __shared__ __align__(16) __nv_bfloat16 Bsb[2][128 * SMEM_STRIDE];
    __shared__ float sbias[128];
    __shared__ float ssqs[128];

    const int tid = threadIdx.x;
    const int wid = tid >> 5, lane = tid & 31;
    const int m0 = blockIdx.x * 128;
    const int n0g = blockIdx.y * 128;
    const int mw = wid >> 1;
    const int nw = wid & 1;

    if (tid < 128) { sbias[tid] = __ldg(&bias[n0g + tid]); ssqs[tid] = 0.f; }

    const uint32_t As_base = smem_u32(Asb);
    const uint32_t Bs_base = smem_u32(Bsb);
    const uint32_t BUFB = 128 * SMEM_STRIDE * 2;

    const int r0c = tid >> 2, sub0 = tid & 3;
    const int r1c = (tid + 256) >> 2, sub1 = (tid + 256) & 3;

#define LOAD_TILE(b, kt) do {                                                   \
    int k0 = (kt) * 32;                                                         \
    const __nv_bfloat16* Asrc = ((k0 >> 8) < 2) ? Ahi : Alo;                    \
    int kc = k0 & 255;                                                          \
    uint32_t Ad = As_base + (b) * BUFB;                                         \
    uint32_t Bd = Bs_base + (b) * BUFB;                                         \
    {                                                                           \
        int grow = m0 + r0c;                                                    \
        const void* src = Asrc + (size_t)grow * 256 + kc + sub0 * 8;            \
        int pb = (grow < N_NODES) ? 16 : 0;                                     \
        asm volatile("cp.async.cg.shared.global [%0], [%1], 16, %2;"            \
            :: "r"(Ad + r0c * 80 + sub0 * 16), "l"(src), "r"(pb));              \
        grow = m0 + r1c;                                                        \
        src = Asrc + (size_t)grow * 256 + kc + sub1 * 8;                        \
        pb = (grow < N_NODES) ? 16 : 0;                                         \
        asm volatile("cp.async.cg.shared.global [%0], [%1], 16, %2;"            \
            :: "r"(Ad + r1c * 80 + sub1 * 16), "l"(src), "r"(pb));              \
    }                                                                           \
    {                                                                           \
        const void* src = Wp + (size_t)(n0g + r0c) * 768 + k0 + sub0 * 8;       \
        asm volatile("cp.async.cg.shared.global [%0], [%1], 16;"                \
            :: "r"(Bd + r0c * 80 + sub0 * 16), "l"(src));                       \
        src = Wp + (size_t)(n0g + r1c) * 768 + k0 + sub1 * 8;                   \
        asm volatile("cp.async.cg.shared.global [%0], [%1], 16;"                \
            :: "r"(Bd + r1c * 80 + sub1 * 16), "l"(src));                       \
    }                                                                           \
    asm volatile("cp.async.commit_group;" ::: "memory");                        \
} while (0)

    float acc[2][8][4];
#pragma unroll
    for (int mt = 0; mt < 2; mt++)
#pragma unroll
        for (int nt = 0; nt < 8; nt++)
#pragma unroll
            for (int v = 0; v < 4; v++) acc[mt][nt][v] = 0.f;

    LOAD_TILE(0, 0);

    const int NK = 24;
    for (int kt = 0; kt < NK; kt++) {
        int b = kt & 1;
        if (kt + 1 < NK) {
            LOAD_TILE(b ^ 1, kt + 1);
            asm volatile("cp.async.wait_group 1;" ::: "memory");
        } else {
            asm volatile("cp.async.wait_group 0;" ::: "memory");
        }
        __syncthreads();

        uint32_t Au = As_base + b * BUFB;
        uint32_t Bu = Bs_base + b * BUFB;
#pragma unroll
        for (int kk = 0; kk < 32; kk += 16) {
            uint32_t a[2][4];
#pragma unroll
            for (int mt = 0; mt < 2; mt++) {
                uint32_t addr = Au + (mw * 32 + mt * 16 + (lane & 15)) * 80
                              + (kk + ((lane >> 4) << 3)) * 2;
                asm volatile("ldmatrix.sync.aligned.m8n8.x4.shared.b16 {%0,%1,%2,%3}, [%4];"
                    : "=r"(a[mt][0]), "=r"(a[mt][1]), "=r"(a[mt][2]), "=r"(a[mt][3])
                    : "r"(addr));
            }
            uint32_t bf[4][4];
#pragma unroll
            for (int nq = 0; nq < 4; nq++) {
                uint32_t addr = Bu + (nw * 64 + nq * 16 + (lane & 7) + ((lane >> 4) << 3)) * 80
                              + (kk + (((lane >> 3) & 1) << 3)) * 2;
                asm volatile("ldmatrix.sync.aligned.m8n8.x4.shared.b16 {%0,%1,%2,%3}, [%4];"
                    : "=r"(bf[nq][0]), "=r"(bf[nq][1]), "=r"(bf[nq][2]), "=r"(bf[nq][3])
                    : "r"(addr));
            }
#pragma unroll
            for (int mt = 0; mt < 2; mt++)
#pragma unroll
                for (int nt = 0; nt < 8; nt++) {
                    int nq = nt >> 1, hv = (nt & 1) << 1;
                    asm volatile(
                        "mma.sync.aligned.m16n8k16.row.col.f32.bf16.bf16.f32 "
                        "{%0,%1,%2,%3}, {%4,%5,%6,%7}, {%8,%9}, {%0,%1,%2,%3};"
                        : "+f"(acc[mt][nt][0]), "+f"(acc[mt][nt][1]),
                          "+f"(acc[mt][nt][2]), "+f"(acc[mt][nt][3])
                        : "r"(a[mt][0]), "r"(a[mt][1]), "r"(a[mt][2]), "r"(a[mt][3]),
                          "r"(bf[nq][hv]), "r"(bf[nq][hv + 1]));
                }
        }
        __syncthreads();
    }
#undef LOAD_TILE

    const int lr = lane >> 2, lc = (lane & 3) * 2;

    if (EPI == 1) {
#pragma unroll
        for (int mt = 0; mt < 2; mt++) {
            float sa = 0.f, sb = 0.f;
#pragma unroll
            for (int nt = 0; nt < 8; nt++) {
                int col = nw * 64 + nt * 8 + lc;
                float v0 = acc[mt][nt][0] + sbias[col];
                float v1 = acc[mt][nt][1] + sbias[col + 1];
                float v2 = acc[mt][nt][2] + sbias[col];
                float v3 = acc[mt][nt][3] + sbias[col + 1];
                acc[mt][nt][0] = v0; acc[mt][nt][1] = v1;
                acc[mt][nt][2] = v2; acc[mt][nt][3] = v3;
                sa += v0 * v0 + v1 * v1;
                sb += v2 * v2 + v3 * v3;
            }
            // quad shuffle-reduce over the 4 lanes sharing a row (lane>>2 == lr),
            // then a single atomic per quad (4x fewer smem atomics).
            sa += __shfl_xor_sync(0xFFFFFFFFu, sa, 1);
            sa += __shfl_xor_sync(0xFFFFFFFFu, sa, 2);
            sb += __shfl_xor_sync(0xFFFFFFFFu, sb, 1);
            sb += __shfl_xor_sync(0xFFFFFFFFu, sb, 2);
            if ((lane & 3) == 0) {
                int rla = mw * 32 + mt * 16 + lr;
                atomicAdd(&ssqs[rla], sa);
                atomicAdd(&ssqs[rla + 8], sb);
            }
        }
        __syncthreads();
        if (tid < 128) {
            int gr = m0 + tid;
            if (gr < N_NODES) g_ssq[(size_t)gr * 2 + blockIdx.y] = ssqs[tid];
        }
        __nv_bfloat16* H = g_uhhi;
        __nv_bfloat16* L = g_uhlo;
#pragma unroll
        for (int mt = 0; mt < 2; mt++) {
            int ra = m0 + mw * 32 + mt * 16 + lr;
            int rb = ra + 8;
#pragma unroll
            for (int nt = 0; nt < 8; nt++) {
                int gcol = n0g + nw * 64 + nt * 8 + lc;
                if (ra < N_NODES) {
                    float v0 = fmaxf(acc[mt][nt][0], 0.f);
                    float v1 = fmaxf(acc[mt][nt][1], 0.f);
                    __nv_bfloat16 h0, l0, h1, l1;
                    bsplit(v0, h0, l0); bsplit(v1, h1, l1);
                    __nv_bfloat162 hh; hh.x = h0; hh.y = h1;
                    __nv_bfloat162 ll; ll.x = l0; ll.y = l1;
                    *(__nv_bfloat162*)(H + (size_t)ra * 256 + gcol) = hh;
                    *(__nv_bfloat162*)(L + (size_t)ra * 256 + gcol) = ll;
                }
                if (rb < N_NODES) {
                    float v0 = fmaxf(acc[mt][nt][2], 0.f);
                    float v1 = fmaxf(acc[mt][nt][3], 0.f);
                    __nv_bfloat16 h0, l0, h1, l1;
                    bsplit(v0, h0, l0); bsplit(v1, h1, l1);
                    __nv_bfloat162 hh; hh.x = h0; hh.y = h1;
                    __nv_bfloat162 ll; ll.x = l0; ll.y = l1;
                    *(__nv_bfloat162*)(H + (size_t)rb * 256 + gcol) = hh;
                    *(__nv_bfloat162*)(L + (size_t)rb * 256 + gcol) = ll;
                }
            }
        }
    } else {
        float* o = (blockIdx.y == 0) ? (float*)o0 : (float*)o1;
#pragma unroll
        for (int mt = 0; mt < 2; mt++) {
            int ra = m0 + mw * 32 + mt * 16 + lr;
            int rb = ra + 8;
            float sA = 0.f, sB = 0.f;
            if (ra < N_NODES) {
                float t = g_ssq[(size_t)ra * 2] + g_ssq[(size_t)ra * 2 + 1];
                sA = 1.0f / fmaxf(sqrtf(t), 1e-12f);
            }
            if (rb < N_NODES) {
                float t = g_ssq[(size_t)rb * 2] + g_ssq[(size_t)rb * 2 + 1];
                sB = 1.0f / fmaxf(sqrtf(t), 1e-12f);
            }
#pragma unroll
            for (int nt = 0; nt < 8; nt++) {
                int col = nw * 64 + nt * 8 + lc;
                float b0v = sbias[col], b1v = sbias[col + 1];
                if (ra < N_NODES) {
                    float2 v;
                    v.x = acc[mt][nt][0] * sA + b0v;
                    v.y = acc[mt][nt][1] * sA + b1v;
                    *(float2*)(o + (size_t)ra * 128 + col) = v;
                }
                if (rb < N_NODES) {
                    float2 v;
                    v.x = acc[mt][nt][2] * sB + b0v;
                    v.y = acc[mt][nt][3] * sB + b1v;
                    *(float2*)(o + (size_t)rb * 128 + col) = v;
                }
            }
        }
    }
}

// ------- gather2 + norm2 + layer3 projection fused (h2 never hits gmem) ----
__global__ void gather_l3_kernel(const float* __restrict__ W3l,
                                 const float* __restrict__ W3r) {
    int gw = (blockIdx.x * blockDim.x + threadIdx.x) >> 5;
    int lane = threadIdx.x & 31;
    if (gw >= N_NODES) return;
    int beg = g_rowptr[gw], end = g_rowptr[gw + 1];
    float4 acc = make_float4(0.f, 0.f, 0.f, 0.f);
    int j = beg;
    for (; j + 1 < end; j += 2) {
        int s0 = g_csr[j], s1 = g_csr[j + 1];
        float4 v0 = __ldg((const float4*)(g_p2 + (size_t)s0 * 128 + lane * 4));
        float4 v1 = __ldg((const float4*)(g_p2 + (size_t)s1 * 128 + lane * 4));
        acc.x += v0.x + v1.x; acc.y += v0.y + v1.y;
        acc.z += v0.z + v1.z; acc.w += v0.w + v1.w;
    }
    if (j < end) {
        int s0 = g_csr[j];
        float4 v0 = __ldg((const float4*)(g_p2 + (size_t)s0 * 128 + lane * 4));
        acc.x += v0.x; acc.y += v0.y; acc.z += v0.z; acc.w += v0.w;
    }
    float inv = 1.0f / (float)max(end - beg, 1);
    float4 rb = *(const float4*)(g_r2b + (size_t)gw * 128 + lane * 4);
    float4 u;
    u.x = acc.x * inv + rb.x; u.y = acc.y * inv + rb.y;
    u.z = acc.z * inv + rb.z; u.w = acc.w * inv + rb.w;
    float ss = u.x * u.x + u.y * u.y + u.z * u.z + u.w * u.w;
#pragma unroll
    for (int o = 16; o; o >>= 1) ss += __shfl_xor_sync(0xFFFFFFFFu, ss, o);
    float s = 1.0f / fmaxf(sqrtf(ss), 1e-12f);
    u.x = fmaxf(u.x * s, 0.f); u.y = fmaxf(u.y * s, 0.f);
    u.z = fmaxf(u.z * s, 0.f); u.w = fmaxf(u.w * s, 0.f);

    int k = lane * 4;
    float4 wl0 = __ldg((const float4*)(W3l + k));
    float4 wl1 = __ldg((const float4*)(W3l + 128 + k));
    float4 wr0 = __ldg((const float4*)(W3r + k));
    float4 wr1 = __ldg((const float4*)(W3r + 128 + k));
    float a0 = u.x * wl0.x + u.y * wl0.y + u.z * wl0.z + u.w * wl0.w;
    float a1 = u.x * wl1.x + u.y * wl1.y + u.z * wl1.z + u.w * wl1.w;
    float b0 = u.x * wr0.x + u.y * wr0.y + u.z * wr0.z + u.w * wr0.w;
    float b1 = u.x * wr1.x + u.y * wr1.y + u.z * wr1.z + u.w * wr1.w;
#pragma unroll
    for (int o = 16; o; o >>= 1) {
        a0 += __shfl_xor_sync(0xFFFFFFFFu, a0, o);
        a1 += __shfl_xor_sync(0xFFFFFFFFu, a1, o);
        b0 += __shfl_xor_sync(0xFFFFFFFFu, b0, o);
        b1 += __shfl_xor_sync(0xFFFFFFFFu, b1, o);
    }
    if (lane == 0) {
        g_p3[2 * gw + 0] = a0; g_p3[2 * gw + 1] = a1;
        g_r3[2 * gw + 0] = b0; g_r3[2 * gw + 1] = b1;
    }
}

__global__ void l3final_kernel(const float* __restrict__ b3,
                               float* __restrict__ out) {
    int n = blockIdx.x * blockDim.x + threadIdx.x;
    if (n >= N_NODES) return;
    int beg = g_rowptr[n], end = g_rowptr[n + 1];
    float s0 = 0.f, s1 = 0.f;
    for (int j = beg; j < end; j++) {
        int s = g_csr[j];
        float2 v = __ldg((const float2*)(g_p3 + 2 * (size_t)s));
        s0 += v.x; s1 += v.y;
    }
    float inv = 1.0f / (float)max(end - beg, 1);
    float v0 = s0 * inv + g_r3[2 * n + 0] + __ldg(&b3[0]);
    float v1 = s1 * inv + g_r3[2 * n + 1] + __ldg(&b3[1]);
    float nrm = sqrtf(v0 * v0 + v1 * v1);
    float sc = 1.0f / fmaxf(nrm, 1e-12f);
    v0 *= sc; v1 *= sc;
    float mx = fmaxf(v0, v1);
    float lse = mx + logf(expf(v0 - mx) + expf(v1 - mx));
    out[2 * n + 0] = v0 - lse;
    out[2 * n + 1] = v1 - lse;
}

// ---------------- launch ----------------------------------------------------
extern "C" void kernel_launch(void* const* d_in, const int* in_sizes, int n_in,
                              void* d_out, int out_size) {
    const float* x   = (const float*)d_in[0];
    const void*  edg = d_in[1];
    const float* W1l = (const float*)d_in[2];
    const float* W1r = (const float*)d_in[3];
    const float* b1  = (const float*)d_in[4];
    const float* W2l = (const float*)d_in[5];
    const float* W2r = (const float*)d_in[6];
    const float* b2  = (const float*)d_in[7];
    const float* W3l = (const float*)d_in[8];
    const float* W3r = (const float*)d_in[9];
    const float* b3  = (const float*)d_in[10];
    float* out = (float*)d_out;

    void *a1h, *a1l, *uhh, *uhl, *p2p, *r2p, *w1p, *w2p, *bp2;
    cudaGetSymbolAddress(&a1h, g_A1hi);
    cudaGetSymbolAddress(&a1l, g_A1lo);
    cudaGetSymbolAddress(&uhh, g_uhhi);
    cudaGetSymbolAddress(&uhl, g_uhlo);
    cudaGetSymbolAddress(&p2p, g_p2);
    cudaGetSymbolAddress(&r2p, g_r2b);
    cudaGetSymbolAddress(&w1p, g_W1p);
    cudaGetSymbolAddress(&w2p, g_W2p);
    cudaGetSymbolAddress(&bp2, g_bp2);

    const int EB = (N_EDGES + 255) / 256;
    const int WARP_BLKS = (N_NODES * 32 + 255) / 256;
    const int MB = (N_NODES + 127) / 128;   // 782

    // prologue: pack(+zero), CSR build
    pack_kernel<<<768, 256>>>(W1l, W1r, W2l, W2r, b2);
    count_kernel<<<EB, 256>>>(edg);
    scan_kernel<<<1, 1024>>>();
    fill_kernel<<<EB, 256>>>(edg);

    // Layer 1: prep + GEMM with fused relu/bsplit epilogue (+ssq partials)
    prep1_kernel<<<WARP_BLKS, 256>>>(x);
    gemm_mma<1><<<dim3(MB, 2), 256>>>((const __nv_bfloat16*)a1h, (const __nv_bfloat16*)a1l,
                                      (const __nv_bfloat16*)w1p, b1,
                                      (void*)0, (void*)0);

    // Layer 2: GEMM with deferred layer-1 normalization in epilogue
    gemm_mma<2><<<dim3(MB, 2), 256>>>((const __nv_bfloat16*)uhh, (const __nv_bfloat16*)uhl,
                                      (const __nv_bfloat16*)w2p, (const float*)bp2,
                                      p2p, r2p);
    gather_l3_kernel<<<WARP_BLKS, 256>>>(W3l, W3r);

    // Layer 3 finalize
    l3final_kernel<<<(N_NODES + 255) / 256, 256>>>(b3, out);
}